// round 14
// baseline (speedup 1.0000x reference)
#include <cuda_runtime.h>
#include <math.h>
#include <stdint.h>

#define EMBED 256
#define BATCH 32
#define TQ 1024
#define TKV 512
#define NMELS_R 320
#define NLAYERS 4
#define SQRT_HALF 0.70710678118654752440f
#define KTILE 16

// smem word layout: As[2][128][20] (5120 w), Bs[2][16][264] (8448 w) => 54272 bytes
#define AS_BUF 2560
#define BS_BASE 5120
#define BS_BUF 4224
#define GSMEM_BYTES 54272

// ---------------- scratch (device globals; no allocation allowed) ----------------
__device__ float g_h   [BATCH * TQ * EMBED];
__device__ float g_h2  [BATCH * TQ * EMBED];
__device__ float g_ctx [BATCH * TQ * EMBED];
__device__ float g_qin [BATCH * TQ * EMBED];
__device__ float g_kin [BATCH * TKV * EMBED];
__device__ float g_kout[BATCH * TKV * EMBED];
__device__ float g_vout[BATCH * TKV * EMBED];
__device__ float g_big [BATCH * TQ * 512];
__device__ float g_peq [TQ * EMBED];
__device__ float g_pek [TKV * EMBED];

// ---------------- cp.async helpers ----------------
__device__ __forceinline__ uint32_t smem_u32(const void* p) {
    return (uint32_t)__cvta_generic_to_shared(p);
}
__device__ __forceinline__ void cp_async16(uint32_t dst, const void* src, int src_bytes) {
    asm volatile("cp.async.cg.shared.global [%0], [%1], 16, %2;\n"
                 :: "r"(dst), "l"(src), "r"(src_bytes));
}
__device__ __forceinline__ void cp_async_commit() { asm volatile("cp.async.commit_group;\n"); }
__device__ __forceinline__ void cp_async_wait0()  { asm volatile("cp.async.wait_group 0;\n"); }

// ---------------- 2-op truncation split (verified R12 @2.1e-5) ----------------
__device__ __forceinline__ void split_tf32(float x, uint32_t& hi, uint32_t& lo) {
    uint32_t h = __float_as_uint(x) & 0xFFFFE000u;
    hi = h;
    lo = __float_as_uint(x - __uint_as_float(h));
}
__device__ __forceinline__ void mma_tf32(float* c, const uint32_t* a, const uint32_t* b) {
    asm volatile(
        "mma.sync.aligned.m16n8k8.row.col.f32.tf32.tf32.f32 "
        "{%0,%1,%2,%3}, {%4,%5,%6,%7}, {%8,%9}, {%0,%1,%2,%3};"
        : "+f"(c[0]), "+f"(c[1]), "+f"(c[2]), "+f"(c[3])
        : "r"(a[0]), "r"(a[1]), "r"(a[2]), "r"(a[3]), "r"(b[0]), "r"(b[1]));
}

// ---------------- positional encoding (VERIFIED R5 @5.5e-7 — DO NOT CHANGE) ----------------
__global__ void posenc_kernel(float* __restrict__ pe, int T, float rate) {
    int idx = blockIdx.x * blockDim.x + threadIdx.x;
    if (idx >= T * EMBED) return;
    int t = idx / EMBED;
    int c = idx - t * EMBED;
    double e = (double)(2.0f * (float)(c >> 1) / 256.0f);
    float power = (float)pow(10000.0, e);
    float recip = 1.0f / power;
    float p  = (float)t;
    float t1 = p * rate;
    float t2 = t1 * recip;
    float angle = p * t2;
    double a = (double)angle;
    pe[idx] = (c & 1) ? (float)cos(a) : (float)sin(a);
}

__global__ void addpe_kernel(const float* __restrict__ x, const float* __restrict__ pe,
                             float* __restrict__ y, int period) {
    long long idx = (long long)blockIdx.x * blockDim.x + threadIdx.x;
    long long r = idx >> 8;
    int c = (int)(idx & 255);
    int t = (int)(r & (period - 1));
    y[idx] = x[idx] + pe[t * EMBED + c];
}

// ---------------- TF32 tensor-core GEMM, 128x256 CTA tile, 64x64 warp tiles ----------------
enum AMode { A_NORMAL = 0, A_CONV = 2 };
enum Epi   { E_RELU = 0, E_BIAS = 1, E_NONE = 2, E_SCALE = 3, E_RESID = 4 };

// C[M,N] = epi( A[M,K] @ B[K,N] );  TRANSB: B stored [N,K].
// CTA 128x256x16, 8 warps (2x4), warp tile 64x64 via 4x8 m16n8k8, 3xTF32 split.
// MMA issue is split-term-outermost so the same accumulator is revisited only
// every 16 instructions (kills the acc-RAW latency chains of the per-(i,j) order).
// Per-accumulator accumulation order (hh -> lh -> hl) is UNCHANGED => bit-identical.
template<int AMODE, bool TRANSB, int EPI>
__global__ void __launch_bounds__(256, 1)
gemm_kernel(const float* __restrict__ A, const float* __restrict__ Bm,
            float* __restrict__ C,
            const float* __restrict__ bias,
            const float* __restrict__ resid,
            int M, int N, int K,
            long long sA, long long sB, long long sC,
            int dil, float scale)
{
    extern __shared__ float sm[];

    const int bz = blockIdx.z;
    A  += bz * sA;
    Bm += bz * sB;
    C  += bz * sC;

    const int row0 = blockIdx.y * 128;
    const int col0 = blockIdx.x * 256;
    const int tid  = threadIdx.x;
    const int lane = tid & 31;
    const int warp = tid >> 5;
    const int m0 = (warp >> 2) * 64;   // 2 row-bands
    const int n0 = (warp & 3) * 64;    // 4 col-bands
    const int g = lane >> 2;
    const int t = lane & 3;

    const int nk = K / KTILE;

    // ---- tile loaders ----
    auto load_A = [&](int kt, int b) {
#pragma unroll
        for (int u = 0; u < 2; u++) {
            const int idx = tid + u * 256;
            const int r  = idx >> 2;
            const int kc = (idx & 3) * 4;
            const int gr = row0 + r;
            const int kg = kt * KTILE + kc;
            const float* src;
            int sz = 16;
            if (AMODE == A_CONV) {
                const int tap = kg >> 8;
                const int ci  = kg & 255;
                const int shift = (4 - tap) * dil;
                const int b_ = gr >> 10;
                const int t_ = gr & 1023;
                if (t_ >= shift)
                    src = A + ((long long)((b_ << 10) + (t_ - shift))) * EMBED + ci;
                else { src = A; sz = 0; }
            } else {
                src = A + (long long)gr * K + kg;
            }
            cp_async16(smem_u32(sm) + (uint32_t)((b * AS_BUF + r * 20 + kc) * 4), src, sz);
        }
    };
    auto load_B = [&](int kt, int b) {
#pragma unroll
        for (int u = 0; u < 4; u++) {
            const int idx = tid + u * 256;
            const int kk = idx >> 6;
            const int nc = (idx & 63) * 4;
            const int gn = col0 + nc;
            const float* src = Bm + (long long)(kt * KTILE + kk) * N + gn;
            int sz = (gn < N) ? 16 : 0;
            if (gn >= N) src = Bm;
            cp_async16(smem_u32(sm) + (uint32_t)((BS_BASE + b * BS_BUF + kk * 264 + nc) * 4), src, sz);
        }
    };
    float4 tb[4];
    auto ldg_Bt = [&](int kt) {
#pragma unroll
        for (int u = 0; u < 4; u++) {
            const int idx = tid + u * 256;
            const int n  = idx >> 2;
            const int kc = (idx & 3) * 4;
            const int gn = col0 + n;
            tb[u] = (gn < N) ? *(const float4*)&Bm[(long long)gn * K + kt * KTILE + kc]
                             : make_float4(0.f, 0.f, 0.f, 0.f);
        }
    };
    auto sts_Bt = [&](int b) {
#pragma unroll
        for (int u = 0; u < 4; u++) {
            const int idx = tid + u * 256;
            const int n  = idx >> 2;
            const int kc = (idx & 3) * 4;
            float* base = sm + BS_BASE + b * BS_BUF;
            base[(kc + 0) * 264 + n] = tb[u].x;
            base[(kc + 1) * 264 + n] = tb[u].y;
            base[(kc + 2) * 264 + n] = tb[u].z;
            base[(kc + 3) * 264 + n] = tb[u].w;
        }
    };

    float acc[4][8][4];
#pragma unroll
    for (int i = 0; i < 4; i++)
#pragma unroll
        for (int j = 0; j < 8; j++)
#pragma unroll
            for (int r = 0; r < 4; r++) acc[i][j][r] = 0.0f;

    // ---- prologue ----
    load_A(0, 0);
    if (!TRANSB) {
        load_B(0, 0);
        cp_async_commit();
        cp_async_wait0();
    } else {
        cp_async_commit();
        ldg_Bt(0);
        cp_async_wait0();
        sts_Bt(0);
    }
    __syncthreads();

    for (int kt = 0; kt < nk; kt++) {
        const int cur = kt & 1;
        const int nxt = cur ^ 1;
        const bool more = (kt + 1 < nk);

        if (more) {
            load_A(kt + 1, nxt);
            if (!TRANSB) load_B(kt + 1, nxt);
            cp_async_commit();
            if (TRANSB) ldg_Bt(kt + 1);
        }

        const float* AsC = sm + cur * AS_BUF;
        const float* BsC = sm + BS_BASE + cur * BS_BUF;

        // ---- compute on cur: 2 k8 steps ----
#pragma unroll
        for (int step = 0; step < 2; step++) {
            const int kk = step * 8;
            uint32_t ahi[4][4], alo[4][4];
#pragma unroll
            for (int i = 0; i < 4; i++) {
                const int r = m0 + i * 16 + g;
                split_tf32(AsC[r * 20 + kk + t],           ahi[i][0], alo[i][0]);
                split_tf32(AsC[(r + 8) * 20 + kk + t],     ahi[i][1], alo[i][1]);
                split_tf32(AsC[r * 20 + kk + t + 4],       ahi[i][2], alo[i][2]);
                split_tf32(AsC[(r + 8) * 20 + kk + t + 4], ahi[i][3], alo[i][3]);
            }
            // process j in halves; within each half issue term-outermost so the
            // same acc is revisited only every 16 MMAs (no RAW latency chains)
#pragma unroll
            for (int jh = 0; jh < 2; jh++) {
                uint32_t bh[4][2], bl[4][2];
#pragma unroll
                for (int jj = 0; jj < 4; jj++) {
                    const int n = n0 + (jh * 4 + jj) * 8 + g;
                    split_tf32(BsC[(kk + t) * 264 + n],     bh[jj][0], bl[jj][0]);
                    split_tf32(BsC[(kk + t + 4) * 264 + n], bh[jj][1], bl[jj][1]);
                }
#pragma unroll
                for (int i = 0; i < 4; i++)
#pragma unroll
                    for (int jj = 0; jj < 4; jj++)
                        mma_tf32(acc[i][jh * 4 + jj], ahi[i], bh[jj]);
#pragma unroll
                for (int i = 0; i < 4; i++)
#pragma unroll
                    for (int jj = 0; jj < 4; jj++)
                        mma_tf32(acc[i][jh * 4 + jj], alo[i], bh[jj]);
#pragma unroll
                for (int i = 0; i < 4; i++)
#pragma unroll
                    for (int jj = 0; jj < 4; jj++)
                        mma_tf32(acc[i][jh * 4 + jj], ahi[i], bl[jj]);
            }
        }

        if (more && TRANSB) sts_Bt(nxt);
        cp_async_wait0();
        __syncthreads();
    }

    // ---- epilogue ----
#pragma unroll
    for (int i = 0; i < 4; i++) {
#pragma unroll
        for (int j = 0; j < 8; j++) {
            const int cc = col0 + n0 + j * 8 + t * 2;
            if (cc >= N) continue;
#pragma unroll
            for (int half = 0; half < 2; half++) {
                const int r = row0 + m0 + i * 16 + g + half * 8;
                float v0 = acc[i][j][half * 2 + 0];
                float v1 = acc[i][j][half * 2 + 1];
                if (EPI == E_RELU)  { v0 = fmaxf(v0 + bias[cc], 0.0f); v1 = fmaxf(v1 + bias[cc + 1], 0.0f); }
                if (EPI == E_BIAS)  { v0 += bias[cc]; v1 += bias[cc + 1]; }
                if (EPI == E_SCALE) { v0 *= scale; v1 *= scale; }
                if (EPI == E_RESID) {
                    const float2 rs = *(const float2*)&resid[(long long)r * N + cc];
                    v0 = (v0 + bias[cc]     + rs.x) * SQRT_HALF;
                    v1 = (v1 + bias[cc + 1] + rs.y) * SQRT_HALF;
                }
                *(float2*)&C[(long long)r * N + cc] = make_float2(v0, v1);
            }
        }
    }
}

// ---------------- GLU + residual + fused q-input ----------------
__global__ void glu_kernel(const float* __restrict__ y, float* __restrict__ h,
                           float* __restrict__ qin, const float* __restrict__ peq) {
    long long idx = (long long)blockIdx.x * blockDim.x + threadIdx.x;
    if (idx >= (long long)BATCH * TQ * EMBED) return;
    long long r = idx >> 8;
    int c = (int)(idx & 255);
    int t = (int)(r & 1023);
    float a = y[r * 512 + c];
    float g = y[r * 512 + 256 + c];
    float s = 1.0f / (1.0f + expf(-g));
    float hv = (h[idx] + a * s) * SQRT_HALF;
    h[idx] = hv;
    qin[idx] = hv + peq[t * EMBED + c];
}

// ---------------- row softmax over 512 ----------------
__global__ void softmax_kernel(float* __restrict__ x) {
    __shared__ float red[128];
    float* p = x + (long long)blockIdx.x * 512;
    const int tid = threadIdx.x;
    float v[4];
    float m = -1e30f;
#pragma unroll
    for (int i = 0; i < 4; i++) { v[i] = p[tid + i * 128]; m = fmaxf(m, v[i]); }
    red[tid] = m; __syncthreads();
#pragma unroll
    for (int s = 64; s > 0; s >>= 1) {
        if (tid < s) red[tid] = fmaxf(red[tid], red[tid + s]);
        __syncthreads();
    }
    m = red[0];
    __syncthreads();
    float sum = 0.0f;
#pragma unroll
    for (int i = 0; i < 4; i++) { v[i] = expf(v[i] - m); sum += v[i]; }
    red[tid] = sum; __syncthreads();
#pragma unroll
    for (int s = 64; s > 0; s >>= 1) {
        if (tid < s) red[tid] += red[tid + s];
        __syncthreads();
    }
    float inv = 1.0f / red[0];
#pragma unroll
    for (int i = 0; i < 4; i++) p[tid + i * 128] = v[i] * inv;
}

// ---------------- done head ----------------
__global__ void done_kernel(const float* __restrict__ h, const float* __restrict__ w,
                            const float* __restrict__ b, float* __restrict__ out) {
    const int row  = blockIdx.x * 8 + (threadIdx.x >> 5);
    const int lane = threadIdx.x & 31;
    if (row >= BATCH * TQ) return;
    const float* hr = h + (long long)row * EMBED;
    float s0 = 0.0f, s1 = 0.0f;
    for (int k = lane; k < EMBED; k += 32) {
        float hv = hr[k];
        s0 = fmaf(hv, w[k * 2 + 0], s0);
        s1 = fmaf(hv, w[k * 2 + 1], s1);
    }
#pragma unroll
    for (int o = 16; o > 0; o >>= 1) {
        s0 += __shfl_down_sync(0xffffffffu, s0, o);
        s1 += __shfl_down_sync(0xffffffffu, s1, o);
    }
    if (lane == 0) {
        out[row * 2 + 0] = 1.0f / (1.0f + expf(-(s0 + b[0])));
        out[row * 2 + 1] = 1.0f / (1.0f + expf(-(s1 + b[1])));
    }
}

// ---------------- host orchestration ----------------
static inline dim3 gemm_grid(int M, int N, int z) {
    return dim3((N + 255) / 256, M / 128, z);
}

extern "C" void kernel_launch(void* const* d_in, const int* in_sizes, int n_in,
                              void* d_out, int out_size) {
    const float* inputs  = (const float*)d_in[0];
    const float* keys    = (const float*)d_in[1];
    const float* values  = (const float*)d_in[2];
    const float* w_first = (const float*)d_in[3];
    const float* b_first = (const float*)d_in[4];
    const float* fc_w    = (const float*)d_in[5];
    const float* fc_b    = (const float*)d_in[6];
    const float* conv_w  = (const float*)d_in[7];
    const float* conv_b  = (const float*)d_in[8];
    const float* att_w1  = (const float*)d_in[9];
    const float* att_b1  = (const float*)d_in[10];
    const float* att_w2  = (const float*)d_in[11];
    const float* att_b2  = (const float*)d_in[12];
    const float* att_w3  = (const float*)d_in[13];
    const float* att_b3  = (const float*)d_in[14];
    const float* att_wo  = (const float*)d_in[15];
    const float* att_bo  = (const float*)d_in[16];
    const float* w_done  = (const float*)d_in[17];
    const float* b_done  = (const float*)d_in[18];
    const float* w_mel   = (const float*)d_in[19];
    const float* b_mel   = (const float*)d_in[20];

    float* out      = (float*)d_out;
    float* out_mel  = out;
    float* out_done = out + (long long)BATCH * TQ * NMELS_R;
    float* out_h    = out_done + (long long)BATCH * TQ * 2;

    float *h, *h2, *ctx, *qin, *kin, *kout, *vout, *big, *peq, *pek;
    cudaGetSymbolAddress((void**)&h,    g_h);
    cudaGetSymbolAddress((void**)&h2,   g_h2);
    cudaGetSymbolAddress((void**)&ctx,  g_ctx);
    cudaGetSymbolAddress((void**)&qin,  g_qin);
    cudaGetSymbolAddress((void**)&kin,  g_kin);
    cudaGetSymbolAddress((void**)&kout, g_kout);
    cudaGetSymbolAddress((void**)&vout, g_vout);
    cudaGetSymbolAddress((void**)&big,  g_big);
    cudaGetSymbolAddress((void**)&peq,  g_peq);
    cudaGetSymbolAddress((void**)&pek,  g_pek);

    // opt-in dynamic smem (54272 B > 48KB static limit)
    cudaFuncSetAttribute(gemm_kernel<A_NORMAL, false, E_RELU>,  cudaFuncAttributeMaxDynamicSharedMemorySize, GSMEM_BYTES);
    cudaFuncSetAttribute(gemm_kernel<A_NORMAL, false, E_BIAS>,  cudaFuncAttributeMaxDynamicSharedMemorySize, GSMEM_BYTES);
    cudaFuncSetAttribute(gemm_kernel<A_CONV,   false, E_BIAS>,  cudaFuncAttributeMaxDynamicSharedMemorySize, GSMEM_BYTES);
    cudaFuncSetAttribute(gemm_kernel<A_NORMAL, true,  E_NONE>,  cudaFuncAttributeMaxDynamicSharedMemorySize, GSMEM_BYTES);
    cudaFuncSetAttribute(gemm_kernel<A_NORMAL, false, E_SCALE>, cudaFuncAttributeMaxDynamicSharedMemorySize, GSMEM_BYTES);
    cudaFuncSetAttribute(gemm_kernel<A_NORMAL, false, E_RESID>, cudaFuncAttributeMaxDynamicSharedMemorySize, GSMEM_BYTES);

    const int M  = BATCH * TQ;    // 32768
    const int Mk = BATCH * TKV;   // 16384
    const float rsqrt_tk = 1.0f / sqrtf((float)TKV);

    posenc_kernel<<<(TQ * EMBED + 255) / 256, 256>>>(peq, TQ, 1.0f);
    posenc_kernel<<<(TKV * EMBED + 255) / 256, 256>>>(pek, TKV, 2.0f);
    addpe_kernel<<<(Mk * EMBED + 255) / 256, 256>>>(keys, pek, kin, TKV);

    gemm_kernel<A_NORMAL, false, E_RELU><<<gemm_grid(M, EMBED, 1), 256, GSMEM_BYTES>>>(
        inputs, w_first, h2, b_first, nullptr,
        M, EMBED, NMELS_R, 0, 0, 0, 0, 0.0f);
    gemm_kernel<A_NORMAL, false, E_RELU><<<gemm_grid(M, EMBED, 1), 256, GSMEM_BYTES>>>(
        h2, fc_w + 0 * EMBED * EMBED, h, fc_b + 0 * EMBED, nullptr,
        M, EMBED, EMBED, 0, 0, 0, 0, 0.0f);
    gemm_kernel<A_NORMAL, false, E_RELU><<<gemm_grid(M, EMBED, 1), 256, GSMEM_BYTES>>>(
        h, fc_w + 1 * EMBED * EMBED, h2, fc_b + 1 * EMBED, nullptr,
        M, EMBED, EMBED, 0, 0, 0, 0, 0.0f);
    gemm_kernel<A_NORMAL, false, E_RELU><<<gemm_grid(M, EMBED, 1), 256, GSMEM_BYTES>>>(
        h2, fc_w + 2 * EMBED * EMBED, h, fc_b + 2 * EMBED, nullptr,
        M, EMBED, EMBED, 0, 0, 0, 0, 0.0f);

    for (int i = 0; i < NLAYERS; i++) {
        const int dil = 1 << i;
        gemm_kernel<A_CONV, false, E_BIAS><<<gemm_grid(M, 512, 1), 256, GSMEM_BYTES>>>(
            h, conv_w + (long long)i * 5 * EMBED * 512, big,
            conv_b + i * 512, nullptr,
            M, 512, 5 * EMBED, 0, 0, 0, dil, 0.0f);
        glu_kernel<<<(M * EMBED + 255) / 256, 256>>>(big, h, qin, peq);

        gemm_kernel<A_NORMAL, false, E_BIAS><<<gemm_grid(M, EMBED, 1), 256, GSMEM_BYTES>>>(
            qin, att_w2 + (long long)i * EMBED * EMBED, h2,
            att_b2 + i * EMBED, nullptr,
            M, EMBED, EMBED, 0, 0, 0, 0, 0.0f);
        gemm_kernel<A_NORMAL, false, E_BIAS><<<gemm_grid(Mk, EMBED, 1), 256, GSMEM_BYTES>>>(
            kin, att_w1 + (long long)i * EMBED * EMBED, kout,
            att_b1 + i * EMBED, nullptr,
            Mk, EMBED, EMBED, 0, 0, 0, 0, 0.0f);
        gemm_kernel<A_NORMAL, false, E_BIAS><<<gemm_grid(Mk, EMBED, 1), 256, GSMEM_BYTES>>>(
            values, att_w3 + (long long)i * EMBED * EMBED, vout,
            att_b3 + i * EMBED, nullptr,
            Mk, EMBED, EMBED, 0, 0, 0, 0, 0.0f);

        gemm_kernel<A_NORMAL, true, E_NONE><<<gemm_grid(TQ, TKV, BATCH), 256, GSMEM_BYTES>>>(
            h2, kout, big, nullptr, nullptr,
            TQ, TKV, EMBED,
            (long long)TQ * EMBED, (long long)TKV * EMBED, (long long)TQ * TKV,
            0, 0.0f);
        softmax_kernel<<<M, 128>>>(big);
        gemm_kernel<A_NORMAL, false, E_SCALE><<<gemm_grid(TQ, EMBED, BATCH), 256, GSMEM_BYTES>>>(
            big, vout, ctx, nullptr, nullptr,
            TQ, EMBED, TKV,
            (long long)TQ * TKV, (long long)TKV * EMBED, (long long)TQ * EMBED,
            0, rsqrt_tk);
        gemm_kernel<A_NORMAL, false, E_RESID><<<gemm_grid(M, EMBED, 1), 256, GSMEM_BYTES>>>(
            ctx, att_wo + (long long)i * EMBED * EMBED, h,
            att_bo + i * EMBED, h,
            M, EMBED, EMBED, 0, 0, 0, 0, 0.0f);
    }

    gemm_kernel<A_NORMAL, false, E_BIAS><<<gemm_grid(M, NMELS_R, 1), 256, GSMEM_BYTES>>>(
        h, w_mel, out_mel, b_mel, nullptr,
        M, NMELS_R, EMBED, 0, 0, 0, 0, 0.0f);
    done_kernel<<<(M + 7) / 8, 256>>>(h, w_done, b_done, out_done);
    cudaMemcpyAsync(out_h, h, sizeof(float) * (size_t)M * EMBED,
                    cudaMemcpyDeviceToDevice);
}

// round 15
// speedup vs baseline: 1.1407x; 1.1407x over previous
#include <cuda_runtime.h>
#include <math.h>
#include <stdint.h>

#define EMBED 256
#define BATCH 32
#define TQ 1024
#define TKV 512
#define NMELS_R 320
#define NLAYERS 4
#define SQRT_HALF 0.70710678118654752440f
#define KTILE 16

// ---------------- scratch (device globals; no allocation allowed) ----------------
__device__ float g_h   [BATCH * TQ * EMBED];
__device__ float g_h2  [BATCH * TQ * EMBED];
__device__ float g_ctx [BATCH * TQ * EMBED];
__device__ float g_qin [BATCH * TQ * EMBED];
__device__ float g_kin [BATCH * TKV * EMBED];
__device__ float g_kout[BATCH * TKV * EMBED];
__device__ float g_vout[BATCH * TKV * EMBED];
__device__ float g_big [BATCH * TQ * 512];
__device__ float g_peq [TQ * EMBED];
__device__ float g_pek [TKV * EMBED];

// ---------------- cp.async helpers ----------------
__device__ __forceinline__ uint32_t smem_u32(const void* p) {
    return (uint32_t)__cvta_generic_to_shared(p);
}
__device__ __forceinline__ void cp_async16(uint32_t dst, const void* src, int src_bytes) {
    asm volatile("cp.async.cg.shared.global [%0], [%1], 16, %2;\n"
                 :: "r"(dst), "l"(src), "r"(src_bytes));
}
__device__ __forceinline__ void cp_async_commit() { asm volatile("cp.async.commit_group;\n"); }
__device__ __forceinline__ void cp_async_wait0()  { asm volatile("cp.async.wait_group 0;\n"); }

// ---------------- 2-op truncation split (verified R12 @2.1e-5) ----------------
__device__ __forceinline__ void split_tf32(float x, uint32_t& hi, uint32_t& lo) {
    uint32_t h = __float_as_uint(x) & 0xFFFFE000u;
    hi = h;
    lo = __float_as_uint(x - __uint_as_float(h));
}
__device__ __forceinline__ void mma_tf32(float* c, const uint32_t* a, const uint32_t* b) {
    asm volatile(
        "mma.sync.aligned.m16n8k8.row.col.f32.tf32.tf32.f32 "
        "{%0,%1,%2,%3}, {%4,%5,%6,%7}, {%8,%9}, {%0,%1,%2,%3};"
        : "+f"(c[0]), "+f"(c[1]), "+f"(c[2]), "+f"(c[3])
        : "r"(a[0]), "r"(a[1]), "r"(a[2]), "r"(a[3]), "r"(b[0]), "r"(b[1]));
}

// ---------------- positional encoding (VERIFIED R5 @5.5e-7 — DO NOT CHANGE) ----------------
__global__ void posenc_kernel(float* __restrict__ pe, int T, float rate) {
    int idx = blockIdx.x * blockDim.x + threadIdx.x;
    if (idx >= T * EMBED) return;
    int t = idx / EMBED;
    int c = idx - t * EMBED;
    double e = (double)(2.0f * (float)(c >> 1) / 256.0f);
    float power = (float)pow(10000.0, e);
    float recip = 1.0f / power;
    float p  = (float)t;
    float t1 = p * rate;
    float t2 = t1 * recip;
    float angle = p * t2;
    double a = (double)angle;
    pe[idx] = (c & 1) ? (float)cos(a) : (float)sin(a);
}

__global__ void addpe_kernel(const float* __restrict__ x, const float* __restrict__ pe,
                             float* __restrict__ y, int period) {
    long long idx = (long long)blockIdx.x * blockDim.x + threadIdx.x;
    long long r = idx >> 8;
    int c = (int)(idx & 255);
    int t = (int)(r & (period - 1));
    y[idx] = x[idx] + pe[t * EMBED + c];
}

// ---------------- TF32 tensor-core GEMM, 128x128 CTA (4 warps), 2 CTAs/SM ----------------
enum AMode { A_NORMAL = 0, A_CONV = 2 };
enum Epi   { E_RELU = 0, E_BIAS = 1, E_NONE = 2, E_SCALE = 3, E_RESID = 4 };

// C[M,N] = epi( A[M,K] @ B[K,N] );  TRANSB: B stored [N,K].
// CTA 128x128x16, 4 warps (2x2), warp tile 64x64 via 4x8 m16n8k8, 3xTF32 split.
// 128-thread CTAs with occupancy 2: two independent CTAs per SM so that when one
// CTA stalls at its barrier/cp.async-wait, the other keeps the tensor pipe fed.
template<int AMODE, bool TRANSB, int EPI>
__global__ void __launch_bounds__(128, 2)
gemm_kernel(const float* __restrict__ A, const float* __restrict__ Bm,
            float* __restrict__ C,
            const float* __restrict__ bias,
            const float* __restrict__ resid,
            int M, int N, int K,
            long long sA, long long sB, long long sC,
            int dil, float scale)
{
    // Conflict-free padded strides (verified): A stride 20, B stride 136.
    __shared__ float As[2][128][20];
    __shared__ float Bs[2][KTILE][136];

    const int bz = blockIdx.z;
    A  += bz * sA;
    Bm += bz * sB;
    C  += bz * sC;

    const int row0 = blockIdx.y * 128;
    const int col0 = blockIdx.x * 128;
    const int tid  = threadIdx.x;
    const int lane = tid & 31;
    const int warp = tid >> 5;          // 0..3
    const int m0 = (warp >> 1) * 64;    // 2 row-bands
    const int n0 = (warp & 1) * 64;     // 2 col-bands
    const int g = lane >> 2;
    const int t = lane & 3;

    const int nk = K / KTILE;

    // ---- tile loaders (128 threads x 4 float4 each) ----
    auto load_A = [&](int kt, int b) {
#pragma unroll
        for (int u = 0; u < 4; u++) {
            const int idx = tid + u * 128;
            const int r  = idx >> 2;
            const int kc = (idx & 3) * 4;
            const int gr = row0 + r;
            const int kg = kt * KTILE + kc;
            const float* src;
            int sz = 16;
            if (AMODE == A_CONV) {
                const int tap = kg >> 8;
                const int ci  = kg & 255;
                const int shift = (4 - tap) * dil;
                const int b_ = gr >> 10;
                const int t_ = gr & 1023;
                if (t_ >= shift)
                    src = A + ((long long)((b_ << 10) + (t_ - shift))) * EMBED + ci;
                else { src = A; sz = 0; }
            } else {
                src = A + (long long)gr * K + kg;
            }
            cp_async16(smem_u32(&As[b][r][kc]), src, sz);
        }
    };
    auto load_B = [&](int kt, int b) {
#pragma unroll
        for (int u = 0; u < 4; u++) {
            const int idx = tid + u * 128;
            const int kk = idx >> 5;
            const int nc = (idx & 31) * 4;
            const int gn = col0 + nc;
            const float* src = Bm + (long long)(kt * KTILE + kk) * N + gn;
            int sz = (gn < N) ? 16 : 0;
            if (gn >= N) src = Bm;
            cp_async16(smem_u32(&Bs[b][kk][nc]), src, sz);
        }
    };
    float4 tb[4];
    auto ldg_Bt = [&](int kt) {
#pragma unroll
        for (int u = 0; u < 4; u++) {
            const int idx = tid + u * 128;
            const int n  = idx >> 2;
            const int kc = (idx & 3) * 4;
            const int gn = col0 + n;
            tb[u] = (gn < N) ? *(const float4*)&Bm[(long long)gn * K + kt * KTILE + kc]
                             : make_float4(0.f, 0.f, 0.f, 0.f);
        }
    };
    auto sts_Bt = [&](int b) {
#pragma unroll
        for (int u = 0; u < 4; u++) {
            const int idx = tid + u * 128;
            const int n  = idx >> 2;
            const int kc = (idx & 3) * 4;
            Bs[b][kc + 0][n] = tb[u].x;
            Bs[b][kc + 1][n] = tb[u].y;
            Bs[b][kc + 2][n] = tb[u].z;
            Bs[b][kc + 3][n] = tb[u].w;
        }
    };

    float acc[4][8][4];
#pragma unroll
    for (int i = 0; i < 4; i++)
#pragma unroll
        for (int j = 0; j < 8; j++)
#pragma unroll
            for (int r = 0; r < 4; r++) acc[i][j][r] = 0.0f;

    // ---- prologue ----
    load_A(0, 0);
    if (!TRANSB) {
        load_B(0, 0);
        cp_async_commit();
        cp_async_wait0();
    } else {
        cp_async_commit();
        ldg_Bt(0);
        cp_async_wait0();
        sts_Bt(0);
    }
    __syncthreads();

    for (int kt = 0; kt < nk; kt++) {
        const int cur = kt & 1;
        const int nxt = cur ^ 1;
        const bool more = (kt + 1 < nk);

        if (more) {
            load_A(kt + 1, nxt);
            if (!TRANSB) load_B(kt + 1, nxt);
            cp_async_commit();
            if (TRANSB) ldg_Bt(kt + 1);
        }

        // ---- compute on cur: 2 k8 steps ----
#pragma unroll
        for (int step = 0; step < 2; step++) {
            const int kk = step * 8;
            uint32_t ahi[4][4], alo[4][4];
#pragma unroll
            for (int i = 0; i < 4; i++) {
                const int r = m0 + i * 16 + g;
                split_tf32(As[cur][r    ][kk + t    ], ahi[i][0], alo[i][0]);
                split_tf32(As[cur][r + 8][kk + t    ], ahi[i][1], alo[i][1]);
                split_tf32(As[cur][r    ][kk + t + 4], ahi[i][2], alo[i][2]);
                split_tf32(As[cur][r + 8][kk + t + 4], ahi[i][3], alo[i][3]);
            }
#pragma unroll
            for (int jh = 0; jh < 2; jh++) {
                uint32_t bh[4][2], bl[4][2];
#pragma unroll
                for (int jj = 0; jj < 4; jj++) {
                    const int n = n0 + (jh * 4 + jj) * 8 + g;
                    split_tf32(Bs[cur][kk + t    ][n], bh[jj][0], bl[jj][0]);
                    split_tf32(Bs[cur][kk + t + 4][n], bh[jj][1], bl[jj][1]);
                }
#pragma unroll
                for (int i = 0; i < 4; i++)
#pragma unroll
                    for (int jj = 0; jj < 4; jj++)
                        mma_tf32(acc[i][jh * 4 + jj], ahi[i], bh[jj]);
#pragma unroll
                for (int i = 0; i < 4; i++)
#pragma unroll
                    for (int jj = 0; jj < 4; jj++)
                        mma_tf32(acc[i][jh * 4 + jj], alo[i], bh[jj]);
#pragma unroll
                for (int i = 0; i < 4; i++)
#pragma unroll
                    for (int jj = 0; jj < 4; jj++)
                        mma_tf32(acc[i][jh * 4 + jj], ahi[i], bl[jj]);
            }
        }

        if (more && TRANSB) sts_Bt(nxt);
        cp_async_wait0();
        __syncthreads();
    }

    // ---- epilogue ----
#pragma unroll
    for (int i = 0; i < 4; i++) {
#pragma unroll
        for (int j = 0; j < 8; j++) {
            const int cc = col0 + n0 + j * 8 + t * 2;
            if (cc >= N) continue;
#pragma unroll
            for (int half = 0; half < 2; half++) {
                const int r = row0 + m0 + i * 16 + g + half * 8;
                float v0 = acc[i][j][half * 2 + 0];
                float v1 = acc[i][j][half * 2 + 1];
                if (EPI == E_RELU)  { v0 = fmaxf(v0 + bias[cc], 0.0f); v1 = fmaxf(v1 + bias[cc + 1], 0.0f); }
                if (EPI == E_BIAS)  { v0 += bias[cc]; v1 += bias[cc + 1]; }
                if (EPI == E_SCALE) { v0 *= scale; v1 *= scale; }
                if (EPI == E_RESID) {
                    const float2 rs = *(const float2*)&resid[(long long)r * N + cc];
                    v0 = (v0 + bias[cc]     + rs.x) * SQRT_HALF;
                    v1 = (v1 + bias[cc + 1] + rs.y) * SQRT_HALF;
                }
                *(float2*)&C[(long long)r * N + cc] = make_float2(v0, v1);
            }
        }
    }
}

// ---------------- GLU + residual + fused q-input ----------------
__global__ void glu_kernel(const float* __restrict__ y, float* __restrict__ h,
                           float* __restrict__ qin, const float* __restrict__ peq) {
    long long idx = (long long)blockIdx.x * blockDim.x + threadIdx.x;
    if (idx >= (long long)BATCH * TQ * EMBED) return;
    long long r = idx >> 8;
    int c = (int)(idx & 255);
    int t = (int)(r & 1023);
    float a = y[r * 512 + c];
    float g = y[r * 512 + 256 + c];
    float s = 1.0f / (1.0f + expf(-g));
    float hv = (h[idx] + a * s) * SQRT_HALF;
    h[idx] = hv;
    qin[idx] = hv + peq[t * EMBED + c];
}

// ---------------- row softmax over 512 ----------------
__global__ void softmax_kernel(float* __restrict__ x) {
    __shared__ float red[128];
    float* p = x + (long long)blockIdx.x * 512;
    const int tid = threadIdx.x;
    float v[4];
    float m = -1e30f;
#pragma unroll
    for (int i = 0; i < 4; i++) { v[i] = p[tid + i * 128]; m = fmaxf(m, v[i]); }
    red[tid] = m; __syncthreads();
#pragma unroll
    for (int s = 64; s > 0; s >>= 1) {
        if (tid < s) red[tid] = fmaxf(red[tid], red[tid + s]);
        __syncthreads();
    }
    m = red[0];
    __syncthreads();
    float sum = 0.0f;
#pragma unroll
    for (int i = 0; i < 4; i++) { v[i] = expf(v[i] - m); sum += v[i]; }
    red[tid] = sum; __syncthreads();
#pragma unroll
    for (int s = 64; s > 0; s >>= 1) {
        if (tid < s) red[tid] += red[tid + s];
        __syncthreads();
    }
    float inv = 1.0f / red[0];
#pragma unroll
    for (int i = 0; i < 4; i++) p[tid + i * 128] = v[i] * inv;
}

// ---------------- done head ----------------
__global__ void done_kernel(const float* __restrict__ h, const float* __restrict__ w,
                            const float* __restrict__ b, float* __restrict__ out) {
    const int row  = blockIdx.x * 8 + (threadIdx.x >> 5);
    const int lane = threadIdx.x & 31;
    if (row >= BATCH * TQ) return;
    const float* hr = h + (long long)row * EMBED;
    float s0 = 0.0f, s1 = 0.0f;
    for (int k = lane; k < EMBED; k += 32) {
        float hv = hr[k];
        s0 = fmaf(hv, w[k * 2 + 0], s0);
        s1 = fmaf(hv, w[k * 2 + 1], s1);
    }
#pragma unroll
    for (int o = 16; o > 0; o >>= 1) {
        s0 += __shfl_down_sync(0xffffffffu, s0, o);
        s1 += __shfl_down_sync(0xffffffffu, s1, o);
    }
    if (lane == 0) {
        out[row * 2 + 0] = 1.0f / (1.0f + expf(-(s0 + b[0])));
        out[row * 2 + 1] = 1.0f / (1.0f + expf(-(s1 + b[1])));
    }
}

// ---------------- host orchestration ----------------
static inline dim3 gemm_grid(int M, int N, int z) {
    return dim3((N + 127) / 128, M / 128, z);
}

extern "C" void kernel_launch(void* const* d_in, const int* in_sizes, int n_in,
                              void* d_out, int out_size) {
    const float* inputs  = (const float*)d_in[0];
    const float* keys    = (const float*)d_in[1];
    const float* values  = (const float*)d_in[2];
    const float* w_first = (const float*)d_in[3];
    const float* b_first = (const float*)d_in[4];
    const float* fc_w    = (const float*)d_in[5];
    const float* fc_b    = (const float*)d_in[6];
    const float* conv_w  = (const float*)d_in[7];
    const float* conv_b  = (const float*)d_in[8];
    const float* att_w1  = (const float*)d_in[9];
    const float* att_b1  = (const float*)d_in[10];
    const float* att_w2  = (const float*)d_in[11];
    const float* att_b2  = (const float*)d_in[12];
    const float* att_w3  = (const float*)d_in[13];
    const float* att_b3  = (const float*)d_in[14];
    const float* att_wo  = (const float*)d_in[15];
    const float* att_bo  = (const float*)d_in[16];
    const float* w_done  = (const float*)d_in[17];
    const float* b_done  = (const float*)d_in[18];
    const float* w_mel   = (const float*)d_in[19];
    const float* b_mel   = (const float*)d_in[20];

    float* out      = (float*)d_out;
    float* out_mel  = out;
    float* out_done = out + (long long)BATCH * TQ * NMELS_R;
    float* out_h    = out_done + (long long)BATCH * TQ * 2;

    float *h, *h2, *ctx, *qin, *kin, *kout, *vout, *big, *peq, *pek;
    cudaGetSymbolAddress((void**)&h,    g_h);
    cudaGetSymbolAddress((void**)&h2,   g_h2);
    cudaGetSymbolAddress((void**)&ctx,  g_ctx);
    cudaGetSymbolAddress((void**)&qin,  g_qin);
    cudaGetSymbolAddress((void**)&kin,  g_kin);
    cudaGetSymbolAddress((void**)&kout, g_kout);
    cudaGetSymbolAddress((void**)&vout, g_vout);
    cudaGetSymbolAddress((void**)&big,  g_big);
    cudaGetSymbolAddress((void**)&peq,  g_peq);
    cudaGetSymbolAddress((void**)&pek,  g_pek);

    const int M  = BATCH * TQ;    // 32768
    const int Mk = BATCH * TKV;   // 16384
    const float rsqrt_tk = 1.0f / sqrtf((float)TKV);

    posenc_kernel<<<(TQ * EMBED + 255) / 256, 256>>>(peq, TQ, 1.0f);
    posenc_kernel<<<(TKV * EMBED + 255) / 256, 256>>>(pek, TKV, 2.0f);
    addpe_kernel<<<(Mk * EMBED + 255) / 256, 256>>>(keys, pek, kin, TKV);

    gemm_kernel<A_NORMAL, false, E_RELU><<<gemm_grid(M, EMBED, 1), 128>>>(
        inputs, w_first, h2, b_first, nullptr,
        M, EMBED, NMELS_R, 0, 0, 0, 0, 0.0f);
    gemm_kernel<A_NORMAL, false, E_RELU><<<gemm_grid(M, EMBED, 1), 128>>>(
        h2, fc_w + 0 * EMBED * EMBED, h, fc_b + 0 * EMBED, nullptr,
        M, EMBED, EMBED, 0, 0, 0, 0, 0.0f);
    gemm_kernel<A_NORMAL, false, E_RELU><<<gemm_grid(M, EMBED, 1), 128>>>(
        h, fc_w + 1 * EMBED * EMBED, h2, fc_b + 1 * EMBED, nullptr,
        M, EMBED, EMBED, 0, 0, 0, 0, 0.0f);
    gemm_kernel<A_NORMAL, false, E_RELU><<<gemm_grid(M, EMBED, 1), 128>>>(
        h2, fc_w + 2 * EMBED * EMBED, h, fc_b + 2 * EMBED, nullptr,
        M, EMBED, EMBED, 0, 0, 0, 0, 0.0f);

    for (int i = 0; i < NLAYERS; i++) {
        const int dil = 1 << i;
        gemm_kernel<A_CONV, false, E_BIAS><<<gemm_grid(M, 512, 1), 128>>>(
            h, conv_w + (long long)i * 5 * EMBED * 512, big,
            conv_b + i * 512, nullptr,
            M, 512, 5 * EMBED, 0, 0, 0, dil, 0.0f);
        glu_kernel<<<(M * EMBED + 255) / 256, 256>>>(big, h, qin, peq);

        gemm_kernel<A_NORMAL, false, E_BIAS><<<gemm_grid(M, EMBED, 1), 128>>>(
            qin, att_w2 + (long long)i * EMBED * EMBED, h2,
            att_b2 + i * EMBED, nullptr,
            M, EMBED, EMBED, 0, 0, 0, 0, 0.0f);
        gemm_kernel<A_NORMAL, false, E_BIAS><<<gemm_grid(Mk, EMBED, 1), 128>>>(
            kin, att_w1 + (long long)i * EMBED * EMBED, kout,
            att_b1 + i * EMBED, nullptr,
            Mk, EMBED, EMBED, 0, 0, 0, 0, 0.0f);
        gemm_kernel<A_NORMAL, false, E_BIAS><<<gemm_grid(Mk, EMBED, 1), 128>>>(
            values, att_w3 + (long long)i * EMBED * EMBED, vout,
            att_b3 + i * EMBED, nullptr,
            Mk, EMBED, EMBED, 0, 0, 0, 0, 0.0f);

        gemm_kernel<A_NORMAL, true, E_NONE><<<gemm_grid(TQ, TKV, BATCH), 128>>>(
            h2, kout, big, nullptr, nullptr,
            TQ, TKV, EMBED,
            (long long)TQ * EMBED, (long long)TKV * EMBED, (long long)TQ * TKV,
            0, 0.0f);
        softmax_kernel<<<M, 128>>>(big);
        gemm_kernel<A_NORMAL, false, E_SCALE><<<gemm_grid(TQ, EMBED, BATCH), 128>>>(
            big, vout, ctx, nullptr, nullptr,
            TQ, EMBED, TKV,
            (long long)TQ * TKV, (long long)TKV * EMBED, (long long)TQ * EMBED,
            0, rsqrt_tk);
        gemm_kernel<A_NORMAL, false, E_RESID><<<gemm_grid(M, EMBED, 1), 128>>>(
            ctx, att_wo + (long long)i * EMBED * EMBED, h,
            att_bo + i * EMBED, h,
            M, EMBED, EMBED, 0, 0, 0, 0, 0.0f);
    }

    gemm_kernel<A_NORMAL, false, E_BIAS><<<gemm_grid(M, NMELS_R, 1), 128>>>(
        h, w_mel, out_mel, b_mel, nullptr,
        M, NMELS_R, EMBED, 0, 0, 0, 0, 0.0f);
    done_kernel<<<(M + 7) / 8, 256>>>(h, w_done, b_done, out_done);
    cudaMemcpyAsync(out_h, h, sizeof(float) * (size_t)M * EMBED,
                    cudaMemcpyDeviceToDevice);
}

// round 16
// speedup vs baseline: 1.1449x; 1.0037x over previous
#include <cuda_runtime.h>
#include <math.h>
#include <stdint.h>

#define EMBED 256
#define BATCH 32
#define TQ 1024
#define TKV 512
#define NMELS_R 320
#define NLAYERS 4
#define SQRT_HALF 0.70710678118654752440f
#define KTILE 16

// ---------------- scratch (device globals; no allocation allowed) ----------------
__device__ float g_h   [BATCH * TQ * EMBED];
__device__ float g_h2  [BATCH * TQ * EMBED];
__device__ float g_ctx [BATCH * TQ * EMBED];
__device__ float g_qin [BATCH * TQ * EMBED];
__device__ float g_kin [BATCH * TKV * EMBED];
__device__ float g_kout[BATCH * TKV * EMBED];
__device__ float g_vout[BATCH * TKV * EMBED];
__device__ float g_big [BATCH * TQ * 512];
__device__ float g_peq [TQ * EMBED];
__device__ float g_pek [TKV * EMBED];

// ---------------- cp.async helpers ----------------
__device__ __forceinline__ uint32_t smem_u32(const void* p) {
    return (uint32_t)__cvta_generic_to_shared(p);
}
__device__ __forceinline__ void cp_async16(uint32_t dst, const void* src, int src_bytes) {
    asm volatile("cp.async.cg.shared.global [%0], [%1], 16, %2;\n"
                 :: "r"(dst), "l"(src), "r"(src_bytes));
}
__device__ __forceinline__ void cp_async_commit() { asm volatile("cp.async.commit_group;\n"); }
__device__ __forceinline__ void cp_async_wait0()  { asm volatile("cp.async.wait_group 0;\n"); }

// ---------------- 2-op truncation split (verified R12 @2.1e-5) ----------------
__device__ __forceinline__ void split_tf32(float x, uint32_t& hi, uint32_t& lo) {
    uint32_t h = __float_as_uint(x) & 0xFFFFE000u;
    hi = h;
    lo = __float_as_uint(x - __uint_as_float(h));
}
__device__ __forceinline__ void mma_tf32(float* c, const uint32_t* a, const uint32_t* b) {
    asm volatile(
        "mma.sync.aligned.m16n8k8.row.col.f32.tf32.tf32.f32 "
        "{%0,%1,%2,%3}, {%4,%5,%6,%7}, {%8,%9}, {%0,%1,%2,%3};"
        : "+f"(c[0]), "+f"(c[1]), "+f"(c[2]), "+f"(c[3])
        : "r"(a[0]), "r"(a[1]), "r"(a[2]), "r"(a[3]), "r"(b[0]), "r"(b[1]));
}

// ---------------- positional encoding (VERIFIED R5 @5.5e-7 — DO NOT CHANGE) ----------------
__global__ void posenc_kernel(float* __restrict__ pe, int T, float rate) {
    int idx = blockIdx.x * blockDim.x + threadIdx.x;
    if (idx >= T * EMBED) return;
    int t = idx / EMBED;
    int c = idx - t * EMBED;
    double e = (double)(2.0f * (float)(c >> 1) / 256.0f);
    float power = (float)pow(10000.0, e);
    float recip = 1.0f / power;
    float p  = (float)t;
    float t1 = p * rate;
    float t2 = t1 * recip;
    float angle = p * t2;
    double a = (double)angle;
    pe[idx] = (c & 1) ? (float)cos(a) : (float)sin(a);
}

__global__ void addpe_kernel(const float* __restrict__ x, const float* __restrict__ pe,
                             float* __restrict__ y, int period) {
    long long idx = (long long)blockIdx.x * blockDim.x + threadIdx.x;
    long long r = idx >> 8;
    int c = (int)(idx & 255);
    int t = (int)(r & (period - 1));
    y[idx] = x[idx] + pe[t * EMBED + c];
}

// ---------------- TF32 tensor-core GEMM, 128x128 CTA (4 warps), 2 CTAs/SM ----------------
enum AMode { A_NORMAL = 0, A_CONV = 2 };
enum Epi   { E_RELU = 0, E_BIAS = 1, E_NONE = 2, E_SCALE = 3, E_RESID = 4 };

// C[M,N] = epi( A[M,K] @ B[K,N] );  TRANSB: B stored [N,K].
// CTA 128x128x16, 4 warps (2x2), warp tile 64x64 via 4x8 m16n8k8, 3xTF32 split.
// Fragment double-buffering: each k-tile is 4 phases (2 k8-steps x 2 j-halves,
// 48 MMAs each); phase p+1's LDS+split run under phase p's MMAs, so only the
// first phase after the barrier is latency-exposed. Per-acc term order unchanged.
template<int AMODE, bool TRANSB, int EPI>
__global__ void __launch_bounds__(128, 2)
gemm_kernel(const float* __restrict__ A, const float* __restrict__ Bm,
            float* __restrict__ C,
            const float* __restrict__ bias,
            const float* __restrict__ resid,
            int M, int N, int K,
            long long sA, long long sB, long long sC,
            int dil, float scale)
{
    // Conflict-free padded strides (verified): A stride 20, B stride 136.
    __shared__ float As[2][128][20];
    __shared__ float Bs[2][KTILE][136];

    const int bz = blockIdx.z;
    A  += bz * sA;
    Bm += bz * sB;
    C  += bz * sC;

    const int row0 = blockIdx.y * 128;
    const int col0 = blockIdx.x * 128;
    const int tid  = threadIdx.x;
    const int lane = tid & 31;
    const int warp = tid >> 5;          // 0..3
    const int m0 = (warp >> 1) * 64;    // 2 row-bands
    const int n0 = (warp & 1) * 64;     // 2 col-bands
    const int g = lane >> 2;
    const int t = lane & 3;

    const int nk = K / KTILE;

    // ---- tile loaders (128 threads x 4 float4 each) ----
    auto load_A = [&](int kt, int b) {
#pragma unroll
        for (int u = 0; u < 4; u++) {
            const int idx = tid + u * 128;
            const int r  = idx >> 2;
            const int kc = (idx & 3) * 4;
            const int gr = row0 + r;
            const int kg = kt * KTILE + kc;
            const float* src;
            int sz = 16;
            if (AMODE == A_CONV) {
                const int tap = kg >> 8;
                const int ci  = kg & 255;
                const int shift = (4 - tap) * dil;
                const int b_ = gr >> 10;
                const int t_ = gr & 1023;
                if (t_ >= shift)
                    src = A + ((long long)((b_ << 10) + (t_ - shift))) * EMBED + ci;
                else { src = A; sz = 0; }
            } else {
                src = A + (long long)gr * K + kg;
            }
            cp_async16(smem_u32(&As[b][r][kc]), src, sz);
        }
    };
    auto load_B = [&](int kt, int b) {
#pragma unroll
        for (int u = 0; u < 4; u++) {
            const int idx = tid + u * 128;
            const int kk = idx >> 5;
            const int nc = (idx & 31) * 4;
            const int gn = col0 + nc;
            const float* src = Bm + (long long)(kt * KTILE + kk) * N + gn;
            int sz = (gn < N) ? 16 : 0;
            if (gn >= N) src = Bm;
            cp_async16(smem_u32(&Bs[b][kk][nc]), src, sz);
        }
    };
    float4 tb[4];
    auto ldg_Bt = [&](int kt) {
#pragma unroll
        for (int u = 0; u < 4; u++) {
            const int idx = tid + u * 128;
            const int n  = idx >> 2;
            const int kc = (idx & 3) * 4;
            const int gn = col0 + n;
            tb[u] = (gn < N) ? *(const float4*)&Bm[(long long)gn * K + kt * KTILE + kc]
                             : make_float4(0.f, 0.f, 0.f, 0.f);
        }
    };
    auto sts_Bt = [&](int b) {
#pragma unroll
        for (int u = 0; u < 4; u++) {
            const int idx = tid + u * 128;
            const int n  = idx >> 2;
            const int kc = (idx & 3) * 4;
            Bs[b][kc + 0][n] = tb[u].x;
            Bs[b][kc + 1][n] = tb[u].y;
            Bs[b][kc + 2][n] = tb[u].z;
            Bs[b][kc + 3][n] = tb[u].w;
        }
    };

    float acc[4][8][4];
#pragma unroll
    for (int i = 0; i < 4; i++)
#pragma unroll
        for (int j = 0; j < 8; j++)
#pragma unroll
            for (int r = 0; r < 4; r++) acc[i][j][r] = 0.0f;

    // ---- fragment helpers ----
    auto loadAf = [&](int cur, int s, uint32_t (&hi)[4][4], uint32_t (&lo)[4][4]) {
        const int kk = s * 8;
#pragma unroll
        for (int i = 0; i < 4; i++) {
            const int r = m0 + i * 16 + g;
            split_tf32(As[cur][r    ][kk + t    ], hi[i][0], lo[i][0]);
            split_tf32(As[cur][r + 8][kk + t    ], hi[i][1], lo[i][1]);
            split_tf32(As[cur][r    ][kk + t + 4], hi[i][2], lo[i][2]);
            split_tf32(As[cur][r + 8][kk + t + 4], hi[i][3], lo[i][3]);
        }
    };
    auto loadBf = [&](int cur, int s, int jh, uint32_t (&bh)[4][2], uint32_t (&bl)[4][2]) {
        const int kk = s * 8;
#pragma unroll
        for (int jj = 0; jj < 4; jj++) {
            const int n = n0 + (jh * 4 + jj) * 8 + g;
            split_tf32(Bs[cur][kk + t    ][n], bh[jj][0], bl[jj][0]);
            split_tf32(Bs[cur][kk + t + 4][n], bh[jj][1], bl[jj][1]);
        }
    };
    auto mmaPh = [&](int jh, uint32_t (&hi)[4][4], uint32_t (&lo)[4][4],
                     uint32_t (&bh)[4][2], uint32_t (&bl)[4][2]) {
#pragma unroll
        for (int i = 0; i < 4; i++)
#pragma unroll
            for (int jj = 0; jj < 4; jj++)
                mma_tf32(acc[i][jh * 4 + jj], hi[i], bh[jj]);
#pragma unroll
        for (int i = 0; i < 4; i++)
#pragma unroll
            for (int jj = 0; jj < 4; jj++)
                mma_tf32(acc[i][jh * 4 + jj], lo[i], bh[jj]);
#pragma unroll
        for (int i = 0; i < 4; i++)
#pragma unroll
            for (int jj = 0; jj < 4; jj++)
                mma_tf32(acc[i][jh * 4 + jj], hi[i], bl[jj]);
    };

    // ---- prologue ----
    load_A(0, 0);
    if (!TRANSB) {
        load_B(0, 0);
        cp_async_commit();
        cp_async_wait0();
    } else {
        cp_async_commit();
        ldg_Bt(0);
        cp_async_wait0();
        sts_Bt(0);
    }
    __syncthreads();

    uint32_t ahi[2][4][4], alo[2][4][4], bhf[2][4][2], blf[2][4][2];

    for (int kt = 0; kt < nk; kt++) {
        const int cur = kt & 1;
        const int nxt = cur ^ 1;
        const bool more = (kt + 1 < nk);

        if (more) {
            load_A(kt + 1, nxt);
            if (!TRANSB) load_B(kt + 1, nxt);
            cp_async_commit();
            if (TRANSB) ldg_Bt(kt + 1);
        }

        // ---- 4-phase software pipeline over (step, j-half) ----
        loadAf(cur, 0, ahi[0], alo[0]);
        loadBf(cur, 0, 0, bhf[0], blf[0]);
        // p0: prefetch B(0,1); MMA (A0, B00)
        loadBf(cur, 0, 1, bhf[1], blf[1]);
        mmaPh(0, ahi[0], alo[0], bhf[0], blf[0]);
        // p1: prefetch A(1), B(1,0); MMA (A0, B01)
        loadAf(cur, 1, ahi[1], alo[1]);
        loadBf(cur, 1, 0, bhf[0], blf[0]);
        mmaPh(1, ahi[0], alo[0], bhf[1], blf[1]);
        // p2: prefetch B(1,1); MMA (A1, B10)
        loadBf(cur, 1, 1, bhf[1], blf[1]);
        mmaPh(0, ahi[1], alo[1], bhf[0], blf[0]);
        // p3: MMA (A1, B11)
        mmaPh(1, ahi[1], alo[1], bhf[1], blf[1]);

        if (more && TRANSB) sts_Bt(nxt);
        cp_async_wait0();
        __syncthreads();
    }

    // ---- epilogue ----
#pragma unroll
    for (int i = 0; i < 4; i++) {
#pragma unroll
        for (int j = 0; j < 8; j++) {
            const int cc = col0 + n0 + j * 8 + t * 2;
            if (cc >= N) continue;
#pragma unroll
            for (int half = 0; half < 2; half++) {
                const int r = row0 + m0 + i * 16 + g + half * 8;
                float v0 = acc[i][j][half * 2 + 0];
                float v1 = acc[i][j][half * 2 + 1];
                if (EPI == E_RELU)  { v0 = fmaxf(v0 + bias[cc], 0.0f); v1 = fmaxf(v1 + bias[cc + 1], 0.0f); }
                if (EPI == E_BIAS)  { v0 += bias[cc]; v1 += bias[cc + 1]; }
                if (EPI == E_SCALE) { v0 *= scale; v1 *= scale; }
                if (EPI == E_RESID) {
                    const float2 rs = *(const float2*)&resid[(long long)r * N + cc];
                    v0 = (v0 + bias[cc]     + rs.x) * SQRT_HALF;
                    v1 = (v1 + bias[cc + 1] + rs.y) * SQRT_HALF;
                }
                *(float2*)&C[(long long)r * N + cc] = make_float2(v0, v1);
            }
        }
    }
}

// ---------------- GLU + residual + fused q-input ----------------
__global__ void glu_kernel(const float* __restrict__ y, float* __restrict__ h,
                           float* __restrict__ qin, const float* __restrict__ peq) {
    long long idx = (long long)blockIdx.x * blockDim.x + threadIdx.x;
    if (idx >= (long long)BATCH * TQ * EMBED) return;
    long long r = idx >> 8;
    int c = (int)(idx & 255);
    int t = (int)(r & 1023);
    float a = y[r * 512 + c];
    float g = y[r * 512 + 256 + c];
    float s = 1.0f / (1.0f + expf(-g));
    float hv = (h[idx] + a * s) * SQRT_HALF;
    h[idx] = hv;
    qin[idx] = hv + peq[t * EMBED + c];
}

// ---------------- row softmax over 512 ----------------
__global__ void softmax_kernel(float* __restrict__ x) {
    __shared__ float red[128];
    float* p = x + (long long)blockIdx.x * 512;
    const int tid = threadIdx.x;
    float v[4];
    float m = -1e30f;
#pragma unroll
    for (int i = 0; i < 4; i++) { v[i] = p[tid + i * 128]; m = fmaxf(m, v[i]); }
    red[tid] = m; __syncthreads();
#pragma unroll
    for (int s = 64; s > 0; s >>= 1) {
        if (tid < s) red[tid] = fmaxf(red[tid], red[tid + s]);
        __syncthreads();
    }
    m = red[0];
    __syncthreads();
    float sum = 0.0f;
#pragma unroll
    for (int i = 0; i < 4; i++) { v[i] = expf(v[i] - m); sum += v[i]; }
    red[tid] = sum; __syncthreads();
#pragma unroll
    for (int s = 64; s > 0; s >>= 1) {
        if (tid < s) red[tid] += red[tid + s];
        __syncthreads();
    }
    float inv = 1.0f / red[0];
#pragma unroll
    for (int i = 0; i < 4; i++) p[tid + i * 128] = v[i] * inv;
}

// ---------------- done head ----------------
__global__ void done_kernel(const float* __restrict__ h, const float* __restrict__ w,
                            const float* __restrict__ b, float* __restrict__ out) {
    const int row  = blockIdx.x * 8 + (threadIdx.x >> 5);
    const int lane = threadIdx.x & 31;
    if (row >= BATCH * TQ) return;
    const float* hr = h + (long long)row * EMBED;
    float s0 = 0.0f, s1 = 0.0f;
    for (int k = lane; k < EMBED; k += 32) {
        float hv = hr[k];
        s0 = fmaf(hv, w[k * 2 + 0], s0);
        s1 = fmaf(hv, w[k * 2 + 1], s1);
    }
#pragma unroll
    for (int o = 16; o > 0; o >>= 1) {
        s0 += __shfl_down_sync(0xffffffffu, s0, o);
        s1 += __shfl_down_sync(0xffffffffu, s1, o);
    }
    if (lane == 0) {
        out[row * 2 + 0] = 1.0f / (1.0f + expf(-(s0 + b[0])));
        out[row * 2 + 1] = 1.0f / (1.0f + expf(-(s1 + b[1])));
    }
}

// ---------------- host orchestration ----------------
static inline dim3 gemm_grid(int M, int N, int z) {
    return dim3((N + 127) / 128, M / 128, z);
}

extern "C" void kernel_launch(void* const* d_in, const int* in_sizes, int n_in,
                              void* d_out, int out_size) {
    const float* inputs  = (const float*)d_in[0];
    const float* keys    = (const float*)d_in[1];
    const float* values  = (const float*)d_in[2];
    const float* w_first = (const float*)d_in[3];
    const float* b_first = (const float*)d_in[4];
    const float* fc_w    = (const float*)d_in[5];
    const float* fc_b    = (const float*)d_in[6];
    const float* conv_w  = (const float*)d_in[7];
    const float* conv_b  = (const float*)d_in[8];
    const float* att_w1  = (const float*)d_in[9];
    const float* att_b1  = (const float*)d_in[10];
    const float* att_w2  = (const float*)d_in[11];
    const float* att_b2  = (const float*)d_in[12];
    const float* att_w3  = (const float*)d_in[13];
    const float* att_b3  = (const float*)d_in[14];
    const float* att_wo  = (const float*)d_in[15];
    const float* att_bo  = (const float*)d_in[16];
    const float* w_done  = (const float*)d_in[17];
    const float* b_done  = (const float*)d_in[18];
    const float* w_mel   = (const float*)d_in[19];
    const float* b_mel   = (const float*)d_in[20];

    float* out      = (float*)d_out;
    float* out_mel  = out;
    float* out_done = out + (long long)BATCH * TQ * NMELS_R;
    float* out_h    = out_done + (long long)BATCH * TQ * 2;

    float *h, *h2, *ctx, *qin, *kin, *kout, *vout, *big, *peq, *pek;
    cudaGetSymbolAddress((void**)&h,    g_h);
    cudaGetSymbolAddress((void**)&h2,   g_h2);
    cudaGetSymbolAddress((void**)&ctx,  g_ctx);
    cudaGetSymbolAddress((void**)&qin,  g_qin);
    cudaGetSymbolAddress((void**)&kin,  g_kin);
    cudaGetSymbolAddress((void**)&kout, g_kout);
    cudaGetSymbolAddress((void**)&vout, g_vout);
    cudaGetSymbolAddress((void**)&big,  g_big);
    cudaGetSymbolAddress((void**)&peq,  g_peq);
    cudaGetSymbolAddress((void**)&pek,  g_pek);

    const int M  = BATCH * TQ;    // 32768
    const int Mk = BATCH * TKV;   // 16384
    const float rsqrt_tk = 1.0f / sqrtf((float)TKV);

    posenc_kernel<<<(TQ * EMBED + 255) / 256, 256>>>(peq, TQ, 1.0f);
    posenc_kernel<<<(TKV * EMBED + 255) / 256, 256>>>(pek, TKV, 2.0f);
    addpe_kernel<<<(Mk * EMBED + 255) / 256, 256>>>(keys, pek, kin, TKV);

    gemm_kernel<A_NORMAL, false, E_RELU><<<gemm_grid(M, EMBED, 1), 128>>>(
        inputs, w_first, h2, b_first, nullptr,
        M, EMBED, NMELS_R, 0, 0, 0, 0, 0.0f);
    gemm_kernel<A_NORMAL, false, E_RELU><<<gemm_grid(M, EMBED, 1), 128>>>(
        h2, fc_w + 0 * EMBED * EMBED, h, fc_b + 0 * EMBED, nullptr,
        M, EMBED, EMBED, 0, 0, 0, 0, 0.0f);
    gemm_kernel<A_NORMAL, false, E_RELU><<<gemm_grid(M, EMBED, 1), 128>>>(
        h, fc_w + 1 * EMBED * EMBED, h2, fc_b + 1 * EMBED, nullptr,
        M, EMBED, EMBED, 0, 0, 0, 0, 0.0f);
    gemm_kernel<A_NORMAL, false, E_RELU><<<gemm_grid(M, EMBED, 1), 128>>>(
        h2, fc_w + 2 * EMBED * EMBED, h, fc_b + 2 * EMBED, nullptr,
        M, EMBED, EMBED, 0, 0, 0, 0, 0.0f);

    for (int i = 0; i < NLAYERS; i++) {
        const int dil = 1 << i;
        gemm_kernel<A_CONV, false, E_BIAS><<<gemm_grid(M, 512, 1), 128>>>(
            h, conv_w + (long long)i * 5 * EMBED * 512, big,
            conv_b + i * 512, nullptr,
            M, 512, 5 * EMBED, 0, 0, 0, dil, 0.0f);
        glu_kernel<<<(M * EMBED + 255) / 256, 256>>>(big, h, qin, peq);

        gemm_kernel<A_NORMAL, false, E_BIAS><<<gemm_grid(M, EMBED, 1), 128>>>(
            qin, att_w2 + (long long)i * EMBED * EMBED, h2,
            att_b2 + i * EMBED, nullptr,
            M, EMBED, EMBED, 0, 0, 0, 0, 0.0f);
        gemm_kernel<A_NORMAL, false, E_BIAS><<<gemm_grid(Mk, EMBED, 1), 128>>>(
            kin, att_w1 + (long long)i * EMBED * EMBED, kout,
            att_b1 + i * EMBED, nullptr,
            Mk, EMBED, EMBED, 0, 0, 0, 0, 0.0f);
        gemm_kernel<A_NORMAL, false, E_BIAS><<<gemm_grid(Mk, EMBED, 1), 128>>>(
            values, att_w3 + (long long)i * EMBED * EMBED, vout,
            att_b3 + i * EMBED, nullptr,
            Mk, EMBED, EMBED, 0, 0, 0, 0, 0.0f);

        gemm_kernel<A_NORMAL, true, E_NONE><<<gemm_grid(TQ, TKV, BATCH), 128>>>(
            h2, kout, big, nullptr, nullptr,
            TQ, TKV, EMBED,
            (long long)TQ * EMBED, (long long)TKV * EMBED, (long long)TQ * TKV,
            0, 0.0f);
        softmax_kernel<<<M, 128>>>(big);
        gemm_kernel<A_NORMAL, false, E_SCALE><<<gemm_grid(TQ, EMBED, BATCH), 128>>>(
            big, vout, ctx, nullptr, nullptr,
            TQ, EMBED, TKV,
            (long long)TQ * TKV, (long long)TKV * EMBED, (long long)TQ * EMBED,
            0, rsqrt_tk);
        gemm_kernel<A_NORMAL, false, E_RESID><<<gemm_grid(M, EMBED, 1), 128>>>(
            ctx, att_wo + (long long)i * EMBED * EMBED, h,
            att_bo + i * EMBED, h,
            M, EMBED, EMBED, 0, 0, 0, 0, 0.0f);
    }

    gemm_kernel<A_NORMAL, false, E_BIAS><<<gemm_grid(M, NMELS_R, 1), 128>>>(
        h, w_mel, out_mel, b_mel, nullptr,
        M, NMELS_R, EMBED, 0, 0, 0, 0, 0.0f);
    done_kernel<<<(M + 7) / 8, 256>>>(h, w_done, b_done, out_done);
    cudaMemcpyAsync(out_h, h, sizeof(float) * (size_t)M * EMBED,
                    cudaMemcpyDeviceToDevice);
}

// round 17
// speedup vs baseline: 1.6438x; 1.4358x over previous
#include <cuda_runtime.h>
#include <math.h>
#include <stdint.h>

#define EMBED 256
#define BATCH 32
#define TQ 1024
#define TKV 512
#define NMELS_R 320
#define NLAYERS 4
#define SQRT_HALF 0.70710678118654752440f
#define KTILE 16

// ---------------- scratch (device globals; no allocation allowed) ----------------
__device__ float g_h   [BATCH * TQ * EMBED];
__device__ float g_h2  [BATCH * TQ * EMBED];
__device__ float g_ctx [BATCH * TQ * EMBED];
__device__ float g_qin [BATCH * TQ * EMBED];
__device__ float g_kin [BATCH * TKV * EMBED];
__device__ float g_kout[BATCH * TKV * EMBED];
__device__ float g_vout[BATCH * TKV * EMBED];
__device__ float g_big [BATCH * TQ * 512];
__device__ float g_peq [TQ * EMBED];
__device__ float g_pek [TKV * EMBED];

// ---------------- cp.async helpers ----------------
__device__ __forceinline__ uint32_t smem_u32(const void* p) {
    return (uint32_t)__cvta_generic_to_shared(p);
}
__device__ __forceinline__ void cp_async16(uint32_t dst, const void* src, int src_bytes) {
    asm volatile("cp.async.cg.shared.global [%0], [%1], 16, %2;\n"
                 :: "r"(dst), "l"(src), "r"(src_bytes));
}
__device__ __forceinline__ void cp_async_commit() { asm volatile("cp.async.commit_group;\n"); }
__device__ __forceinline__ void cp_async_wait0()  { asm volatile("cp.async.wait_group 0;\n"); }

// ---------------- bf16x2 rounded split+pack ----------------
// Packs (x0 -> low half, x1 -> high half) rounded bf16 pair into hi;
// residuals (x - bf16(x)) rounded-packed into lo. Combined coverage ~16-17
// mantissa bits; per-product error ~3*2^-16 (lo*lo dropped).
__device__ __forceinline__ void split_bf16x2(float x0, float x1, uint32_t& hi, uint32_t& lo) {
    uint32_t d;
    asm("cvt.rn.bf16x2.f32 %0, %1, %2;" : "=r"(d) : "f"(x1), "f"(x0));
    float h1 = __uint_as_float(d & 0xFFFF0000u);
    float h0 = __uint_as_float(d << 16);
    float l1 = x1 - h1;
    float l0 = x0 - h0;
    uint32_t dl;
    asm("cvt.rn.bf16x2.f32 %0, %1, %2;" : "=r"(dl) : "f"(l1), "f"(l0));
    hi = d; lo = dl;
}
__device__ __forceinline__ void mma_bf16(float* c, const uint32_t* a, const uint32_t* b) {
    asm volatile(
        "mma.sync.aligned.m16n8k16.row.col.f32.bf16.bf16.f32 "
        "{%0,%1,%2,%3}, {%4,%5,%6,%7}, {%8,%9}, {%0,%1,%2,%3};"
        : "+f"(c[0]), "+f"(c[1]), "+f"(c[2]), "+f"(c[3])
        : "r"(a[0]), "r"(a[1]), "r"(a[2]), "r"(a[3]), "r"(b[0]), "r"(b[1]));
}

// ---------------- positional encoding (VERIFIED R5 @5.5e-7 — DO NOT CHANGE) ----------------
__global__ void posenc_kernel(float* __restrict__ pe, int T, float rate) {
    int idx = blockIdx.x * blockDim.x + threadIdx.x;
    if (idx >= T * EMBED) return;
    int t = idx / EMBED;
    int c = idx - t * EMBED;
    double e = (double)(2.0f * (float)(c >> 1) / 256.0f);
    float power = (float)pow(10000.0, e);
    float recip = 1.0f / power;
    float p  = (float)t;
    float t1 = p * rate;
    float t2 = t1 * recip;
    float angle = p * t2;
    double a = (double)angle;
    pe[idx] = (c & 1) ? (float)cos(a) : (float)sin(a);
}

__global__ void addpe_kernel(const float* __restrict__ x, const float* __restrict__ pe,
                             float* __restrict__ y, int period) {
    long long idx = (long long)blockIdx.x * blockDim.x + threadIdx.x;
    long long r = idx >> 8;
    int c = (int)(idx & 255);
    int t = (int)(r & (period - 1));
    y[idx] = x[idx] + pe[t * EMBED + c];
}

// ---------------- bf16x2 tensor-core GEMM, 128x128 CTA (4 warps), 2 CTAs/SM ----------------
enum AMode { A_NORMAL = 0, A_CONV = 2 };
enum Epi   { E_RELU = 0, E_BIAS = 1, E_NONE = 2, E_SCALE = 3, E_RESID = 4 };

// C[M,N] = epi( A[M,K] @ B[K,N] );  TRANSB: B stored [N,K].
// CTA 128x128x16, 4 warps (2x2), warp tile 64x64 via 4x8 m16n8k16 bf16, 2-split
// (3 products: hh, lh, hl) — half the tensor cycles of the tf32x3 path.
// Smem strides re-derived for k-pair (2t, 2t+1) fragment access:
//   A stride 24: banks 24g+2t distinct over (g,t). B stride 132: 132*2t+g distinct.
template<int AMODE, bool TRANSB, int EPI>
__global__ void __launch_bounds__(128, 2)
gemm_kernel(const float* __restrict__ A, const float* __restrict__ Bm,
            float* __restrict__ C,
            const float* __restrict__ bias,
            const float* __restrict__ resid,
            int M, int N, int K,
            long long sA, long long sB, long long sC,
            int dil, float scale)
{
    __shared__ float As[2][128][24];
    __shared__ float Bs[2][KTILE][132];

    const int bz = blockIdx.z;
    A  += bz * sA;
    Bm += bz * sB;
    C  += bz * sC;

    const int row0 = blockIdx.y * 128;
    const int col0 = blockIdx.x * 128;
    const int tid  = threadIdx.x;
    const int lane = tid & 31;
    const int warp = tid >> 5;          // 0..3
    const int m0 = (warp >> 1) * 64;    // 2 row-bands
    const int n0 = (warp & 1) * 64;     // 2 col-bands
    const int g = lane >> 2;
    const int t = lane & 3;

    const int nk = K / KTILE;

    // ---- tile loaders (128 threads x 4 float4 each) ----
    auto load_A = [&](int kt, int b) {
#pragma unroll
        for (int u = 0; u < 4; u++) {
            const int idx = tid + u * 128;
            const int r  = idx >> 2;
            const int kc = (idx & 3) * 4;
            const int gr = row0 + r;
            const int kg = kt * KTILE + kc;
            const float* src;
            int sz = 16;
            if (AMODE == A_CONV) {
                const int tap = kg >> 8;
                const int ci  = kg & 255;
                const int shift = (4 - tap) * dil;
                const int b_ = gr >> 10;
                const int t_ = gr & 1023;
                if (t_ >= shift)
                    src = A + ((long long)((b_ << 10) + (t_ - shift))) * EMBED + ci;
                else { src = A; sz = 0; }
            } else {
                src = A + (long long)gr * K + kg;
            }
            cp_async16(smem_u32(&As[b][r][kc]), src, sz);
        }
    };
    auto load_B = [&](int kt, int b) {
#pragma unroll
        for (int u = 0; u < 4; u++) {
            const int idx = tid + u * 128;
            const int kk = idx >> 5;
            const int nc = (idx & 31) * 4;
            const int gn = col0 + nc;
            const float* src = Bm + (long long)(kt * KTILE + kk) * N + gn;
            int sz = (gn < N) ? 16 : 0;
            if (gn >= N) src = Bm;
            cp_async16(smem_u32(&Bs[b][kk][nc]), src, sz);
        }
    };
    float4 tb[4];
    auto ldg_Bt = [&](int kt) {
#pragma unroll
        for (int u = 0; u < 4; u++) {
            const int idx = tid + u * 128;
            const int n  = idx >> 2;
            const int kc = (idx & 3) * 4;
            const int gn = col0 + n;
            tb[u] = (gn < N) ? *(const float4*)&Bm[(long long)gn * K + kt * KTILE + kc]
                             : make_float4(0.f, 0.f, 0.f, 0.f);
        }
    };
    auto sts_Bt = [&](int b) {
#pragma unroll
        for (int u = 0; u < 4; u++) {
            const int idx = tid + u * 128;
            const int n  = idx >> 2;
            const int kc = (idx & 3) * 4;
            Bs[b][kc + 0][n] = tb[u].x;
            Bs[b][kc + 1][n] = tb[u].y;
            Bs[b][kc + 2][n] = tb[u].z;
            Bs[b][kc + 3][n] = tb[u].w;
        }
    };

    float acc[4][8][4];
#pragma unroll
    for (int i = 0; i < 4; i++)
#pragma unroll
        for (int j = 0; j < 8; j++)
#pragma unroll
            for (int r = 0; r < 4; r++) acc[i][j][r] = 0.0f;

    // ---- prologue ----
    load_A(0, 0);
    if (!TRANSB) {
        load_B(0, 0);
        cp_async_commit();
        cp_async_wait0();
    } else {
        cp_async_commit();
        ldg_Bt(0);
        cp_async_wait0();
        sts_Bt(0);
    }
    __syncthreads();

    for (int kt = 0; kt < nk; kt++) {
        const int cur = kt & 1;
        const int nxt = cur ^ 1;
        const bool more = (kt + 1 < nk);

        if (more) {
            load_A(kt + 1, nxt);
            if (!TRANSB) load_B(kt + 1, nxt);
            cp_async_commit();
            if (TRANSB) ldg_Bt(kt + 1);
        }

        // ---- compute on cur: one k16 step, bf16x2 fragments ----
        uint32_t ahi[4][4], alo[4][4];
#pragma unroll
        for (int i = 0; i < 4; i++) {
            const int r = m0 + i * 16 + g;
            const float2 p0 = *(const float2*)&As[cur][r    ][2 * t];
            const float2 p1 = *(const float2*)&As[cur][r + 8][2 * t];
            const float2 p2 = *(const float2*)&As[cur][r    ][2 * t + 8];
            const float2 p3 = *(const float2*)&As[cur][r + 8][2 * t + 8];
            split_bf16x2(p0.x, p0.y, ahi[i][0], alo[i][0]);
            split_bf16x2(p1.x, p1.y, ahi[i][1], alo[i][1]);
            split_bf16x2(p2.x, p2.y, ahi[i][2], alo[i][2]);
            split_bf16x2(p3.x, p3.y, ahi[i][3], alo[i][3]);
        }
#pragma unroll
        for (int jh = 0; jh < 2; jh++) {
            uint32_t bh[4][2], bl[4][2];
#pragma unroll
            for (int jj = 0; jj < 4; jj++) {
                const int n = n0 + (jh * 4 + jj) * 8 + g;
                split_bf16x2(Bs[cur][2 * t    ][n], Bs[cur][2 * t + 1][n], bh[jj][0], bl[jj][0]);
                split_bf16x2(Bs[cur][2 * t + 8][n], Bs[cur][2 * t + 9][n], bh[jj][1], bl[jj][1]);
            }
#pragma unroll
            for (int i = 0; i < 4; i++)
#pragma unroll
                for (int jj = 0; jj < 4; jj++)
                    mma_bf16(acc[i][jh * 4 + jj], ahi[i], bh[jj]);
#pragma unroll
            for (int i = 0; i < 4; i++)
#pragma unroll
                for (int jj = 0; jj < 4; jj++)
                    mma_bf16(acc[i][jh * 4 + jj], alo[i], bh[jj]);
#pragma unroll
            for (int i = 0; i < 4; i++)
#pragma unroll
                for (int jj = 0; jj < 4; jj++)
                    mma_bf16(acc[i][jh * 4 + jj], ahi[i], bl[jj]);
        }

        if (more && TRANSB) sts_Bt(nxt);
        cp_async_wait0();
        __syncthreads();
    }

    // ---- epilogue (C frag layout identical to tf32 path) ----
#pragma unroll
    for (int i = 0; i < 4; i++) {
#pragma unroll
        for (int j = 0; j < 8; j++) {
            const int cc = col0 + n0 + j * 8 + t * 2;
            if (cc >= N) continue;
#pragma unroll
            for (int half = 0; half < 2; half++) {
                const int r = row0 + m0 + i * 16 + g + half * 8;
                float v0 = acc[i][j][half * 2 + 0];
                float v1 = acc[i][j][half * 2 + 1];
                if (EPI == E_RELU)  { v0 = fmaxf(v0 + bias[cc], 0.0f); v1 = fmaxf(v1 + bias[cc + 1], 0.0f); }
                if (EPI == E_BIAS)  { v0 += bias[cc]; v1 += bias[cc + 1]; }
                if (EPI == E_SCALE) { v0 *= scale; v1 *= scale; }
                if (EPI == E_RESID) {
                    const float2 rs = *(const float2*)&resid[(long long)r * N + cc];
                    v0 = (v0 + bias[cc]     + rs.x) * SQRT_HALF;
                    v1 = (v1 + bias[cc + 1] + rs.y) * SQRT_HALF;
                }
                *(float2*)&C[(long long)r * N + cc] = make_float2(v0, v1);
            }
        }
    }
}

// ---------------- GLU + residual + fused q-input ----------------
__global__ void glu_kernel(const float* __restrict__ y, float* __restrict__ h,
                           float* __restrict__ qin, const float* __restrict__ peq) {
    long long idx = (long long)blockIdx.x * blockDim.x + threadIdx.x;
    if (idx >= (long long)BATCH * TQ * EMBED) return;
    long long r = idx >> 8;
    int c = (int)(idx & 255);
    int t = (int)(r & 1023);
    float a = y[r * 512 + c];
    float g = y[r * 512 + 256 + c];
    float s = 1.0f / (1.0f + expf(-g));
    float hv = (h[idx] + a * s) * SQRT_HALF;
    h[idx] = hv;
    qin[idx] = hv + peq[t * EMBED + c];
}

// ---------------- row softmax over 512 ----------------
__global__ void softmax_kernel(float* __restrict__ x) {
    __shared__ float red[128];
    float* p = x + (long long)blockIdx.x * 512;
    const int tid = threadIdx.x;
    float v[4];
    float m = -1e30f;
#pragma unroll
    for (int i = 0; i < 4; i++) { v[i] = p[tid + i * 128]; m = fmaxf(m, v[i]); }
    red[tid] = m; __syncthreads();
#pragma unroll
    for (int s = 64; s > 0; s >>= 1) {
        if (tid < s) red[tid] = fmaxf(red[tid], red[tid + s]);
        __syncthreads();
    }
    m = red[0];
    __syncthreads();
    float sum = 0.0f;
#pragma unroll
    for (int i = 0; i < 4; i++) { v[i] = expf(v[i] - m); sum += v[i]; }
    red[tid] = sum; __syncthreads();
#pragma unroll
    for (int s = 64; s > 0; s >>= 1) {
        if (tid < s) red[tid] += red[tid + s];
        __syncthreads();
    }
    float inv = 1.0f / red[0];
#pragma unroll
    for (int i = 0; i < 4; i++) p[tid + i * 128] = v[i] * inv;
}

// ---------------- done head ----------------
__global__ void done_kernel(const float* __restrict__ h, const float* __restrict__ w,
                            const float* __restrict__ b, float* __restrict__ out) {
    const int row  = blockIdx.x * 8 + (threadIdx.x >> 5);
    const int lane = threadIdx.x & 31;
    if (row >= BATCH * TQ) return;
    const float* hr = h + (long long)row * EMBED;
    float s0 = 0.0f, s1 = 0.0f;
    for (int k = lane; k < EMBED; k += 32) {
        float hv = hr[k];
        s0 = fmaf(hv, w[k * 2 + 0], s0);
        s1 = fmaf(hv, w[k * 2 + 1], s1);
    }
#pragma unroll
    for (int o = 16; o > 0; o >>= 1) {
        s0 += __shfl_down_sync(0xffffffffu, s0, o);
        s1 += __shfl_down_sync(0xffffffffu, s1, o);
    }
    if (lane == 0) {
        out[row * 2 + 0] = 1.0f / (1.0f + expf(-(s0 + b[0])));
        out[row * 2 + 1] = 1.0f / (1.0f + expf(-(s1 + b[1])));
    }
}

// ---------------- host orchestration ----------------
static inline dim3 gemm_grid(int M, int N, int z) {
    return dim3((N + 127) / 128, M / 128, z);
}

extern "C" void kernel_launch(void* const* d_in, const int* in_sizes, int n_in,
                              void* d_out, int out_size) {
    const float* inputs  = (const float*)d_in[0];
    const float* keys    = (const float*)d_in[1];
    const float* values  = (const float*)d_in[2];
    const float* w_first = (const float*)d_in[3];
    const float* b_first = (const float*)d_in[4];
    const float* fc_w    = (const float*)d_in[5];
    const float* fc_b    = (const float*)d_in[6];
    const float* conv_w  = (const float*)d_in[7];
    const float* conv_b  = (const float*)d_in[8];
    const float* att_w1  = (const float*)d_in[9];
    const float* att_b1  = (const float*)d_in[10];
    const float* att_w2  = (const float*)d_in[11];
    const float* att_b2  = (const float*)d_in[12];
    const float* att_w3  = (const float*)d_in[13];
    const float* att_b3  = (const float*)d_in[14];
    const float* att_wo  = (const float*)d_in[15];
    const float* att_bo  = (const float*)d_in[16];
    const float* w_done  = (const float*)d_in[17];
    const float* b_done  = (const float*)d_in[18];
    const float* w_mel   = (const float*)d_in[19];
    const float* b_mel   = (const float*)d_in[20];

    float* out      = (float*)d_out;
    float* out_mel  = out;
    float* out_done = out + (long long)BATCH * TQ * NMELS_R;
    float* out_h    = out_done + (long long)BATCH * TQ * 2;

    float *h, *h2, *ctx, *qin, *kin, *kout, *vout, *big, *peq, *pek;
    cudaGetSymbolAddress((void**)&h,    g_h);
    cudaGetSymbolAddress((void**)&h2,   g_h2);
    cudaGetSymbolAddress((void**)&ctx,  g_ctx);
    cudaGetSymbolAddress((void**)&qin,  g_qin);
    cudaGetSymbolAddress((void**)&kin,  g_kin);
    cudaGetSymbolAddress((void**)&kout, g_kout);
    cudaGetSymbolAddress((void**)&vout, g_vout);
    cudaGetSymbolAddress((void**)&big,  g_big);
    cudaGetSymbolAddress((void**)&peq,  g_peq);
    cudaGetSymbolAddress((void**)&pek,  g_pek);

    const int M  = BATCH * TQ;    // 32768
    const int Mk = BATCH * TKV;   // 16384
    const float rsqrt_tk = 1.0f / sqrtf((float)TKV);

    posenc_kernel<<<(TQ * EMBED + 255) / 256, 256>>>(peq, TQ, 1.0f);
    posenc_kernel<<<(TKV * EMBED + 255) / 256, 256>>>(pek, TKV, 2.0f);
    addpe_kernel<<<(Mk * EMBED + 255) / 256, 256>>>(keys, pek, kin, TKV);

    gemm_kernel<A_NORMAL, false, E_RELU><<<gemm_grid(M, EMBED, 1), 128>>>(
        inputs, w_first, h2, b_first, nullptr,
        M, EMBED, NMELS_R, 0, 0, 0, 0, 0.0f);
    gemm_kernel<A_NORMAL, false, E_RELU><<<gemm_grid(M, EMBED, 1), 128>>>(
        h2, fc_w + 0 * EMBED * EMBED, h, fc_b + 0 * EMBED, nullptr,
        M, EMBED, EMBED, 0, 0, 0, 0, 0.0f);
    gemm_kernel<A_NORMAL, false, E_RELU><<<gemm_grid(M, EMBED, 1), 128>>>(
        h, fc_w + 1 * EMBED * EMBED, h2, fc_b + 1 * EMBED, nullptr,
        M, EMBED, EMBED, 0, 0, 0, 0, 0.0f);
    gemm_kernel<A_NORMAL, false, E_RELU><<<gemm_grid(M, EMBED, 1), 128>>>(
        h2, fc_w + 2 * EMBED * EMBED, h, fc_b + 2 * EMBED, nullptr,
        M, EMBED, EMBED, 0, 0, 0, 0, 0.0f);

    for (int i = 0; i < NLAYERS; i++) {
        const int dil = 1 << i;
        gemm_kernel<A_CONV, false, E_BIAS><<<gemm_grid(M, 512, 1), 128>>>(
            h, conv_w + (long long)i * 5 * EMBED * 512, big,
            conv_b + i * 512, nullptr,
            M, 512, 5 * EMBED, 0, 0, 0, dil, 0.0f);
        glu_kernel<<<(M * EMBED + 255) / 256, 256>>>(big, h, qin, peq);

        gemm_kernel<A_NORMAL, false, E_BIAS><<<gemm_grid(M, EMBED, 1), 128>>>(
            qin, att_w2 + (long long)i * EMBED * EMBED, h2,
            att_b2 + i * EMBED, nullptr,
            M, EMBED, EMBED, 0, 0, 0, 0, 0.0f);
        gemm_kernel<A_NORMAL, false, E_BIAS><<<gemm_grid(Mk, EMBED, 1), 128>>>(
            kin, att_w1 + (long long)i * EMBED * EMBED, kout,
            att_b1 + i * EMBED, nullptr,
            Mk, EMBED, EMBED, 0, 0, 0, 0, 0.0f);
        gemm_kernel<A_NORMAL, false, E_BIAS><<<gemm_grid(Mk, EMBED, 1), 128>>>(
            values, att_w3 + (long long)i * EMBED * EMBED, vout,
            att_b3 + i * EMBED, nullptr,
            Mk, EMBED, EMBED, 0, 0, 0, 0, 0.0f);

        gemm_kernel<A_NORMAL, true, E_NONE><<<gemm_grid(TQ, TKV, BATCH), 128>>>(
            h2, kout, big, nullptr, nullptr,
            TQ, TKV, EMBED,
            (long long)TQ * EMBED, (long long)TKV * EMBED, (long long)TQ * TKV,
            0, 0.0f);
        softmax_kernel<<<M, 128>>>(big);
        gemm_kernel<A_NORMAL, false, E_SCALE><<<gemm_grid(TQ, EMBED, BATCH), 128>>>(
            big, vout, ctx, nullptr, nullptr,
            TQ, EMBED, TKV,
            (long long)TQ * TKV, (long long)TKV * EMBED, (long long)TQ * EMBED,
            0, rsqrt_tk);
        gemm_kernel<A_NORMAL, false, E_RESID><<<gemm_grid(M, EMBED, 1), 128>>>(
            ctx, att_wo + (long long)i * EMBED * EMBED, h,
            att_bo + i * EMBED, h,
            M, EMBED, EMBED, 0, 0, 0, 0, 0.0f);
    }

    gemm_kernel<A_NORMAL, false, E_BIAS><<<gemm_grid(M, NMELS_R, 1), 128>>>(
        h, w_mel, out_mel, b_mel, nullptr,
        M, NMELS_R, EMBED, 0, 0, 0, 0, 0.0f);
    done_kernel<<<(M + 7) / 8, 256>>>(h, w_done, b_done, out_done);
    cudaMemcpyAsync(out_h, h, sizeof(float) * (size_t)M * EMBED,
                    cudaMemcpyDeviceToDevice);
}